// round 1
// baseline (speedup 1.0000x reference)
#include <cuda_runtime.h>

// Problem shapes (fixed by the reference setup_inputs)
#define NB 32
#define NM 128
#define NN 64
#define ND 256

static __device__ __constant__ const float k_dummy = 0.f; // keep nvcc happy about empty const use

constexpr float EPS_F   = 1e-8f;
constexpr float NEG_BIG = -9e15f;

// Scratch: avg similarity per (b, m). __device__ global per allocation rules.
__device__ float g_avg[NB * NM];

// ---------------------------------------------------------------------------
// Kernel 1: one CTA per (b, m). 512 threads = 16 warps, 4 rows (n) per warp.
// Per row n: warp loads dd[b,m,n,:] (256 f32 = 2 float4/lane) and dia[b,n,:],
// accumulates dot, dd^2, dia^2, |dd|; xor-reduces; folds sim into warp-local
// sum + non-padding count. Final smem reduce across 16 warps -> g_avg[bm].
// dd tile (64 KB) is read exactly once, fully coalesced; dia tile hits L1/L2.
// ---------------------------------------------------------------------------
__global__ void __launch_bounds__(512, 2)
sim_kernel(const float* __restrict__ dia, const float* __restrict__ dd)
{
    const int bm   = blockIdx.x;        // 0 .. NB*NM-1
    const int b    = bm >> 7;           // bm / NM
    const int warp = threadIdx.x >> 5;  // 0..15
    const int lane = threadIdx.x & 31;

    const float4* __restrict__ dd4 =
        reinterpret_cast<const float4*>(dd) + (size_t)bm * (NN * ND / 4);
    const float4* __restrict__ dia4 =
        reinterpret_cast<const float4*>(dia) + (size_t)b * (NN * ND / 4);

    float sim_sum = 0.0f;
    int   cnt     = 0;

    #pragma unroll
    for (int r = 0; r < 4; ++r) {
        const int n = warp * 4 + r;
        const float4* __restrict__ drow = dd4  + n * (ND / 4);
        const float4* __restrict__ qrow = dia4 + n * (ND / 4);

        // Issue all 4 loads up front for MLP.
        const float4 a0 = drow[lane];
        const float4 a1 = drow[lane + 32];
        const float4 q0 = qrow[lane];
        const float4 q1 = qrow[lane + 32];

        float dot = 0.f, dsq = 0.f, qsq = 0.f, dab = 0.f;
        dot = fmaf(a0.x, q0.x, dot); dot = fmaf(a0.y, q0.y, dot);
        dot = fmaf(a0.z, q0.z, dot); dot = fmaf(a0.w, q0.w, dot);
        dot = fmaf(a1.x, q1.x, dot); dot = fmaf(a1.y, q1.y, dot);
        dot = fmaf(a1.z, q1.z, dot); dot = fmaf(a1.w, q1.w, dot);

        dsq = fmaf(a0.x, a0.x, dsq); dsq = fmaf(a0.y, a0.y, dsq);
        dsq = fmaf(a0.z, a0.z, dsq); dsq = fmaf(a0.w, a0.w, dsq);
        dsq = fmaf(a1.x, a1.x, dsq); dsq = fmaf(a1.y, a1.y, dsq);
        dsq = fmaf(a1.z, a1.z, dsq); dsq = fmaf(a1.w, a1.w, dsq);

        qsq = fmaf(q0.x, q0.x, qsq); qsq = fmaf(q0.y, q0.y, qsq);
        qsq = fmaf(q0.z, q0.z, qsq); qsq = fmaf(q0.w, q0.w, qsq);
        qsq = fmaf(q1.x, q1.x, qsq); qsq = fmaf(q1.y, q1.y, qsq);
        qsq = fmaf(q1.z, q1.z, qsq); qsq = fmaf(q1.w, q1.w, qsq);

        dab += fabsf(a0.x) + fabsf(a0.y) + fabsf(a0.z) + fabsf(a0.w);
        dab += fabsf(a1.x) + fabsf(a1.y) + fabsf(a1.z) + fabsf(a1.w);

        // warp reduce all 4 accumulators
        #pragma unroll
        for (int o = 16; o > 0; o >>= 1) {
            dot += __shfl_xor_sync(0xffffffffu, dot, o);
            dsq += __shfl_xor_sync(0xffffffffu, dsq, o);
            qsq += __shfl_xor_sync(0xffffffffu, qsq, o);
            dab += __shfl_xor_sync(0xffffffffu, dab, o);
        }

        // sim for this row (all lanes hold the same value)
        const float denom = fmaxf(sqrtf(qsq) * sqrtf(dsq), EPS_F);
        sim_sum += dot / denom;     // padded row: dot==0 -> contributes 0
        cnt     += (dab != 0.0f);   // reference mask: abs-sum == 0 means padding
    }

    __shared__ float s_sum[16];
    __shared__ int   s_cnt[16];
    if (lane == 0) { s_sum[warp] = sim_sum; s_cnt[warp] = cnt; }
    __syncthreads();

    if (threadIdx.x < 16) {
        float v = s_sum[threadIdx.x];
        int   c = s_cnt[threadIdx.x];
        #pragma unroll
        for (int o = 8; o > 0; o >>= 1) {
            v += __shfl_xor_sync(0x0000ffffu, v, o);
            c += __shfl_xor_sync(0x0000ffffu, c, o);
        }
        if (threadIdx.x == 0) {
            const float dn = (c == 0) ? NEG_BIG : (float)c;
            g_avg[bm] = v / dn;
        }
    }
    (void)k_dummy;
}

// ---------------------------------------------------------------------------
// Kernel 2: one CTA per batch b. First-index argmax over M=128 avg values,
// then conditional float4 copy of the selected 64 KB tile into d_out.
// ---------------------------------------------------------------------------
__global__ void __launch_bounds__(256)
select_kernel(const float* __restrict__ dia, const float* __restrict__ dd,
              float* __restrict__ out)
{
    const int b = blockIdx.x;

    __shared__ float s_val[NM];
    __shared__ int   s_best;
    __shared__ float s_v;

    if (threadIdx.x < NM) s_val[threadIdx.x] = g_avg[b * NM + threadIdx.x];
    __syncthreads();

    if (threadIdx.x == 0) {
        float best = s_val[0];
        int   bi   = 0;
        #pragma unroll 4
        for (int i = 1; i < NM; ++i) {
            const float v = s_val[i];
            if (v > best) { best = v; bi = i; }   // strict > keeps first index on ties
        }
        s_best = bi;
        s_v    = best;
    }
    __syncthreads();

    const float4* __restrict__ src;
    if (s_v > 0.5f) {
        src = reinterpret_cast<const float4*>(dd)
            + ((size_t)b * NM + s_best) * (NN * ND / 4);
    } else {
        src = reinterpret_cast<const float4*>(dia) + (size_t)b * (NN * ND / 4);
    }
    float4* __restrict__ dst = reinterpret_cast<float4*>(out) + (size_t)b * (NN * ND / 4);

    #pragma unroll 4
    for (int i = threadIdx.x; i < NN * ND / 4; i += 256) {
        dst[i] = src[i];
    }
}

// ---------------------------------------------------------------------------
// Launch contract
// ---------------------------------------------------------------------------
extern "C" void kernel_launch(void* const* d_in, const int* in_sizes, int n_in,
                              void* d_out, int out_size)
{
    const float* dia = (const float*)d_in[0];
    const float* dd  = (const float*)d_in[1];
    // Defensive: dia has NB*NN*ND elements (smaller), dd has NB*NM*NN*ND.
    if (n_in >= 2 && in_sizes[0] > in_sizes[1]) {
        const float* t = dia; dia = dd; dd = t;
    }

    sim_kernel<<<NB * NM, 512>>>(dia, dd);
    select_kernel<<<NB, 256>>>(dia, dd, (float*)d_out);
}